// round 15
// baseline (speedup 1.0000x reference)
#include <cuda_runtime.h>
#include <cuda_bf16.h>
#include <cstdint>
#include <cstddef>

#define T_LEN 2048
#define BATCH 16
#define HID   256
#define CIN   512
#define GATES 1024              // 4*H per direction
#define NCOL  2048              // gates for both directions
#define MROWS (BATCH * T_LEN)   // 32768

// ---------------- scratch (static device globals; no allocations) ----------
__device__ float g_proj[(size_t)MROWS * NCOL];            // proj + bias folded in
__device__ float g_hs[(size_t)2 * T_LEN * BATCH * HID];   // h outputs [dir][t][b][c]
__device__ float g_part[128 * 512 * 2];                   // BN partial sums
__device__ float g_wf[4 * 512];                           // folded Wlin
__device__ float g_zc[2];                                 // folded bias
__device__ float g_sampled[BATCH * T_LEN];                // sampled pre-median
__device__ float g_bias[NCOL];                            // bih+bhh per gate col
__device__ __align__(16) __nv_bfloat16 g_xt[(size_t)BATCH * T_LEN * CIN]; // x^T bf16
__device__ __align__(16) __nv_bfloat16 g_wc[(size_t)NCOL * CIN];          // W bf16 [n][k]

// ===================== PTX helpers (compute_103-safe only) ==================
__device__ __forceinline__ uint32_t smem_u32(const void* p) {
    return (uint32_t)__cvta_generic_to_shared(p);
}
__device__ __forceinline__ void cp_async16(uint32_t saddr, const void* g) {
    asm volatile("cp.async.cg.shared.global [%0], [%1], 16;"
                 :: "r"(saddr), "l"(g) : "memory");
}
__device__ __forceinline__ void ldsm_x4(uint32_t* r, uint32_t saddr) {
    asm volatile("ldmatrix.sync.aligned.m8n8.x4.shared.b16 {%0,%1,%2,%3}, [%4];"
                 : "=r"(r[0]), "=r"(r[1]), "=r"(r[2]), "=r"(r[3]) : "r"(saddr));
}
__device__ __forceinline__ void mma16816(float* c, const uint32_t* a, const uint32_t* b) {
    asm volatile("mma.sync.aligned.m16n8k16.row.col.f32.bf16.bf16.f32 "
                 "{%0,%1,%2,%3}, {%4,%5,%6,%7}, {%8,%9}, {%0,%1,%2,%3};"
                 : "+f"(c[0]), "+f"(c[1]), "+f"(c[2]), "+f"(c[3])
                 : "r"(a[0]), "r"(a[1]), "r"(a[2]), "r"(a[3]), "r"(b[0]), "r"(b[1]));
}

// ============================================================================
// K0a: transpose+convert x[b][k][t] fp32 -> g_xt[b][t][k] bf16
// ============================================================================
__global__ void conv_x(const float* __restrict__ X) {
    __shared__ float tile[32][33];
    const int b = blockIdx.z;
    const int k0 = blockIdx.y * 32;
    const int t0 = blockIdx.x * 32;
    const int tx = threadIdx.x, ty = threadIdx.y;   // 32 x 8
#pragma unroll
    for (int i = ty; i < 32; i += 8)
        tile[i][tx] = X[((size_t)b * CIN + k0 + i) * T_LEN + t0 + tx];
    __syncthreads();
#pragma unroll
    for (int i = ty; i < 32; i += 8)
        g_xt[((size_t)b * T_LEN + t0 + i) * CIN + k0 + tx] =
            __float2bfloat16(tile[tx][i]);
}

// K0b: convert W rows -> g_wc bf16
__global__ void conv_w(const float* __restrict__ Wf, const float* __restrict__ Wb) {
    size_t i = (size_t)blockIdx.x * 256 + threadIdx.x;   // < 1048576
    const size_t half = (size_t)GATES * CIN;
    if (i < half) g_wc[i] = __float2bfloat16(Wf[i]);
    else          g_wc[i] = __float2bfloat16(Wb[i - half]);
}

// K0c: combined bias per gate column
__global__ void bias_k(const float* __restrict__ bihF, const float* __restrict__ bhhF,
                       const float* __restrict__ bihB, const float* __restrict__ bhhB) {
    int i = blockIdx.x * 256 + threadIdx.x;   // < 2048
    g_bias[i] = (i < GATES) ? (bihF[i] + bhhF[i])
                            : (bihB[i - GATES] + bhhB[i - GATES]);
}

// ============================================================================
// K1: bf16 TN GEMM via ldmatrix + mma.sync, double-buffered cp.async pipeline.
// ============================================================================
#define ASTR 72                       // bf16 elements per smem row
#define A_BYTES (128 * ASTR * 2)      // 18432
#define STAGE_BYTES (2 * A_BYTES)     // 36864
#define GEMM_SMEM (2 * STAGE_BYTES)   // 73728

__global__ void __launch_bounds__(256) gemm_tc() {
    extern __shared__ __align__(16) char gsm[];
    __shared__ float biasS[128];

    const int tid = threadIdx.x;
    const int wid = tid >> 5, lane = tid & 31;
    const int wm = wid >> 1;
    const int wn = wid & 1;
    const int nt = blockIdx.x;            // 0..15
    const int mt = blockIdx.y;            // 0..255
    const int m0 = mt * 128;
    const int bq = m0 >> 11, t0 = m0 & 2047;

    if (tid < 128) biasS[tid] = g_bias[nt * 128 + tid];

    float acc[2][8][4];
#pragma unroll
    for (int i = 0; i < 2; i++)
#pragma unroll
        for (int j = 0; j < 8; j++)
#pragma unroll
            for (int q = 0; q < 4; q++) acc[i][j][q] = 0.f;

    const int a_row = lane & 15, a_koff = (lane >> 4) * 8;
    const int b_nrow = (lane & 7) + ((lane >> 4) << 3);
    const int b_koff = ((lane >> 3) & 1) * 8;

    const uint32_t sb = smem_u32(gsm);

    auto issue = [&](int kc, int stg) {
        uint32_t base = sb + (uint32_t)stg * STAGE_BYTES;
#pragma unroll
        for (int i = 0; i < 4; i++) {
            int idx = tid + i * 256;        // 0..1023
            int row = idx >> 3, seg = idx & 7;
            cp_async16(base + (uint32_t)(row * ASTR + seg * 8) * 2,
                       &g_xt[((size_t)bq * T_LEN + t0 + row) * CIN + kc * 64 + seg * 8]);
            cp_async16(base + A_BYTES + (uint32_t)(row * ASTR + seg * 8) * 2,
                       &g_wc[((size_t)(nt * 128 + row)) * CIN + kc * 64 + seg * 8]);
        }
        asm volatile("cp.async.commit_group;" ::: "memory");
    };

    issue(0, 0);

    for (int kc = 0; kc < 8; kc++) {
        if (kc + 1 < 8) issue(kc + 1, (kc + 1) & 1);
        if (kc + 1 < 8) asm volatile("cp.async.wait_group 1;" ::: "memory");
        else            asm volatile("cp.async.wait_group 0;" ::: "memory");
        __syncthreads();

        uint32_t base = sb + (uint32_t)(kc & 1) * STAGE_BYTES;
#pragma unroll
        for (int ks = 0; ks < 4; ks++) {
            uint32_t afr[2][4];
#pragma unroll
            for (int m2 = 0; m2 < 2; m2++)
                ldsm_x4(afr[m2],
                        base + (uint32_t)((wm * 32 + m2 * 16 + a_row) * ASTR +
                                          ks * 16 + a_koff) * 2);
            uint32_t bfr[8][2];
#pragma unroll
            for (int p = 0; p < 4; p++) {
                uint32_t r[4];
                ldsm_x4(r, base + A_BYTES +
                           (uint32_t)((wn * 64 + p * 16 + b_nrow) * ASTR +
                                      ks * 16 + b_koff) * 2);
                bfr[p * 2][0] = r[0]; bfr[p * 2][1] = r[1];
                bfr[p * 2 + 1][0] = r[2]; bfr[p * 2 + 1][1] = r[3];
            }
#pragma unroll
            for (int m2 = 0; m2 < 2; m2++)
#pragma unroll
                for (int n8 = 0; n8 < 8; n8++)
                    mma16816(acc[m2][n8], afr[m2], bfr[n8]);
        }
        __syncthreads();
    }

#pragma unroll
    for (int m2 = 0; m2 < 2; m2++)
#pragma unroll
        for (int hf = 0; hf < 2; hf++) {
            int row = m0 + wm * 32 + m2 * 16 + hf * 8 + (lane >> 2);
            int cl = wn * 64 + (lane & 3) * 2;
            float* dst = &g_proj[(size_t)row * NCOL + nt * 128 + cl];
#pragma unroll
            for (int n8 = 0; n8 < 8; n8++) {
                float2 v = make_float2(acc[m2][n8][hf * 2] + biasS[cl + n8 * 8],
                                       acc[m2][n8][hf * 2 + 1] + biasS[cl + n8 * 8 + 1]);
                *(float2*)(dst + n8 * 8) = v;
            }
        }
}

// ============================================================================
// K2: LSTM recurrence, v10 — 1024 threads (8 warps/SMSP), split-k warps.
// Thread = (cell 0..63) x (khalf 0..1) x (16-wide k-slice 0..7).
// Two warps per 4-cell group; partials combined in smem; gate math on khalf0
// warps at 4 cells/warp-instr (MUFU floor unchanged). Proj rows staged to smem
// via cp.async each step (no pv registers). Exact __expf gates; fp32 g_hs.
// ============================================================================
__device__ __forceinline__ void cluster_sync_() {
    asm volatile("barrier.cluster.arrive.aligned;" ::: "memory");
    asm volatile("barrier.cluster.wait.aligned;" ::: "memory");
}
__device__ __forceinline__ float sigm_(float x) { return 1.f / (1.f + __expf(-x)); }
__device__ __forceinline__ float tanh_(float x) {
    x = fminf(fmaxf(x, -15.f), 15.f);
    float e = __expf(2.f * x);
    return (e - 1.f) / (e + 1.f);
}

#define NCHUNK 4
#define CHLEN  512
#define WARMUP 64
#define SERIAL (CHLEN + WARMUP)      // 576
#define HSEG 24                      // ushorts per 16-cell slice (32B + 16B pad)
#define HBUFW (16 * HSEG)            // 384 ushorts per buffer

__global__ void __cluster_dims__(4, 1, 1) __launch_bounds__(1024, 1) lstm_k(
    const float* __restrict__ WhhF, const float* __restrict__ WhhB) {
    __shared__ __align__(16) unsigned short hbuf[NCHUNK * 2 * HBUFW];  // 6144 B
    __shared__ __align__(16) float part0[NCHUNK * 64 * 4];             // 4 KB
    __shared__ __align__(16) float part1[NCHUNK * 64 * 4];             // 4 KB
    __shared__ __align__(16) float psm[NCHUNK * 1024];                 // 16 KB

    const int tid = threadIdx.x;                 // 1024 threads
    const int r = blockIdx.x & 3;                // rank in cluster
    const int chain = blockIdx.x >> 2;           // 0..31
    const int dir = chain >> 4;
    const int b = chain & 15;
    const float* Whh = dir ? WhhB : WhhF;

    const int warp = tid >> 5, lane = tid & 31;
    const int khalf = warp >> 4;                 // k half: 0 or 1
    const int wl = warp & 15;                    // warp-local id
    const int ks = lane & 7;                     // slice within half
    const int cell = wl * 4 + (lane >> 3);       // local cell 0..63
    const int gcg = r * 64 + cell;               // global cell 0..255
    const int kbase = khalf * 128 + ks * 16;

    // weights -> registers: 4 gate rows x 16 k as bf16x2 pairs
    __nv_bfloat162 wreg[4][8];
#pragma unroll
    for (int g = 0; g < 4; g++) {
        const float* wr = Whh + (size_t)(g * 256 + gcg) * HID + kbase;
#pragma unroll
        for (int j = 0; j < 8; j++) {
            float2 f2 = *(const float2*)(wr + 2 * j);
            wreg[g][j] = __floats2bfloat162_rn(f2.x, f2.y);
        }
    }

    float creg[NCHUNK] = {0.f, 0.f, 0.f, 0.f};

    for (int i = tid; i < NCHUNK * 2 * HBUFW / 2; i += 1024)
        ((uint32_t*)hbuf)[i] = 0u;
    __syncthreads();
    cluster_sync_();     // peers' hbuf zeroed before DSMEM traffic

    const __nv_bfloat162 bzero = __floats2bfloat162_rn(0.f, 0.f);
    const uint32_t psm_sb = smem_u32(psm);

    int p = 0;
    for (int s = 0; s < SERIAL; s++) {
        // ---- 1. stage this step's proj rows (4 x 4KB) into smem ----
        {
            const int jj = tid >> 8, seg = tid & 255;
            const int tl = jj * CHLEN - WARMUP + s;
            if (tl >= 0) {
                const int t = dir ? (T_LEN - 1 - tl) : tl;
                cp_async16(psm_sb + (uint32_t)(jj * 1024 + seg * 4) * 4,
                           &g_proj[(size_t)(b * T_LEN + t) * NCOL + dir * GATES +
                                   seg * 4]);
            }
            asm volatile("cp.async.commit_group;" ::: "memory");
        }

        // ---- 2. matvec per chunk: 16 k per thread, butterfly over 8 slices ----
#pragma unroll
        for (int j = 0; j < NCHUNK; j++) {
            const uint4* hv = (const uint4*)(hbuf + (j * 2 + p) * HBUFW +
                                             (khalf * 8 + ks) * HSEG);
            uint4 q0 = hv[0];
            uint4 q1 = hv[1];
            __nv_bfloat162 h0 = *(__nv_bfloat162*)&q0.x;
            __nv_bfloat162 h1 = *(__nv_bfloat162*)&q0.y;
            __nv_bfloat162 h2 = *(__nv_bfloat162*)&q0.z;
            __nv_bfloat162 h3 = *(__nv_bfloat162*)&q0.w;
            __nv_bfloat162 h4 = *(__nv_bfloat162*)&q1.x;
            __nv_bfloat162 h5 = *(__nv_bfloat162*)&q1.y;
            __nv_bfloat162 h6 = *(__nv_bfloat162*)&q1.z;
            __nv_bfloat162 h7 = *(__nv_bfloat162*)&q1.w;

            float fa[4];
#pragma unroll
            for (int g = 0; g < 4; g++) {
                __nv_bfloat162 a = bzero;
                a = __hfma2(wreg[g][0], h0, a);
                a = __hfma2(wreg[g][1], h1, a);
                a = __hfma2(wreg[g][2], h2, a);
                a = __hfma2(wreg[g][3], h3, a);
                a = __hfma2(wreg[g][4], h4, a);
                a = __hfma2(wreg[g][5], h5, a);
                a = __hfma2(wreg[g][6], h6, a);
                a = __hfma2(wreg[g][7], h7, a);
                float2 f = __bfloat1622float2(a);
                fa[g] = f.x + f.y;
            }
#pragma unroll
            for (int m = 1; m < 8; m <<= 1) {
                fa[0] += __shfl_xor_sync(0xffffffffu, fa[0], m);
                fa[1] += __shfl_xor_sync(0xffffffffu, fa[1], m);
                fa[2] += __shfl_xor_sync(0xffffffffu, fa[2], m);
                fa[3] += __shfl_xor_sync(0xffffffffu, fa[3], m);
            }
            if ((lane & 7) == 0) {
                float4 v = make_float4(fa[0], fa[1], fa[2], fa[3]);
                if (khalf) *(float4*)&part1[(j * 64 + cell) * 4] = v;
                else       *(float4*)&part0[(j * 64 + cell) * 4] = v;
            }
        }

        asm volatile("cp.async.wait_group 0;" ::: "memory");
        __syncthreads();   // partials + psm visible to all

        // ---- 3. gate phase: khalf0 warps, 4 cells per warp-instr ----
        if (khalf == 0) {
#pragma unroll
            for (int j = 0; j < NCHUNK; j++) {
                float4 A = *(const float4*)&part0[(j * 64 + cell) * 4];
                float4 B = *(const float4*)&part1[(j * 64 + cell) * 4];
                const float* pr = &psm[j * 1024];
                const float gi = A.x + B.x + pr[gcg];
                const float gf = A.y + B.y + pr[256 + gcg];
                const float gg = A.z + B.z + pr[512 + gcg];
                const float go = A.w + B.w + pr[768 + gcg];

                const int tl = j * CHLEN - WARMUP + s;
                float hval = 0.f;
                if (tl >= 0) {
                    const float iv = sigm_(gi);
                    const float fv = sigm_(gf);
                    const float gv = tanh_(gg);
                    const float ov = sigm_(go);
                    creg[j] = fv * creg[j] + iv * gv;
                    hval = ov * tanh_(creg[j]);
                    if ((lane & 7) == 0 && s >= WARMUP) {
                        const int te = dir ? (T_LEN - 1 - tl) : tl;
                        g_hs[(size_t)((dir * T_LEN + te) * BATCH + b) * HID + gcg] =
                            hval;
                    }
                }
                // pack adjacent cells (lane L with L+8) and store b32
                uint32_t us =
                    (uint32_t)__bfloat16_as_ushort(__float2bfloat16(hval));
                uint32_t other = __shfl_down_sync(0xffffffffu, us, 8);
                if ((lane & 15) == 0) {   // lanes 0,16: cells wl*4+{0,2}
                    const uint32_t pair = us | (other << 16);
                    const int boff = (j * 2 + (p ^ 1)) * HBUFW +
                                     (gcg >> 4) * HSEG + (gcg & 15);
                    *(uint32_t*)&hbuf[boff] = pair;      // local
                    const uint32_t la = smem_u32(&hbuf[boff]);
#pragma unroll
                    for (int pc = 0; pc < 4; pc++) {
                        if (pc == r) continue;
                        uint32_t ra;
                        asm("mapa.shared::cluster.u32 %0, %1, %2;"
                            : "=r"(ra) : "r"(la), "r"(pc));
                        asm volatile("st.shared::cluster.u32 [%0], %1;"
                                     :: "r"(ra), "r"(pair) : "memory");
                    }
                }
            }
        }
        cluster_sync_();   // release own DSMEM h / acquire peers'
        p ^= 1;
    }
}

// ============================================================================
// K3a/K3b: BN stats + fold into Linear
// ============================================================================
__global__ void bn_part() {
    const int ch = threadIdx.x;
    const int dir = ch >> 8, cc = ch & 255;
    const int s0 = blockIdx.x * 1024;
    float sum = 0.f, sq = 0.f;
    const size_t base = (size_t)dir * T_LEN * BATCH * HID + cc;
#pragma unroll 4
    for (int i = 0; i < 1024; i++) {
        float v = g_hs[base + (size_t)(s0 + i) * HID];
        sum += v; sq += v * v;
    }
    g_part[((size_t)blockIdx.x * 512 + ch) * 2]     = sum;
    g_part[((size_t)blockIdx.x * 512 + ch) * 2 + 1] = sq;
}

__global__ void bn_final(const float* __restrict__ gamma,
                         const float* __restrict__ beta,
                         const float* __restrict__ Wlin,
                         const float* __restrict__ blin) {
    __shared__ float red[512];
    const int ch = threadIdx.x;
    double s = 0.0, q = 0.0;
#pragma unroll 8
    for (int i = 0; i < 32; i++) {
        s += (double)g_part[((size_t)i * 512 + ch) * 2];
        q += (double)g_part[((size_t)i * 512 + ch) * 2 + 1];
    }
    const double n = 32768.0;
    float mean = (float)(s / n);
    float var  = (float)(q / n - (s / n) * (s / n));
    float A  = gamma[ch] * rsqrtf(var + 1e-5f);
    float Bc = beta[ch] - mean * A;

    g_wf[ch]       = Wlin[ch] * A;
    g_wf[512 + ch] = Wlin[512 + ch] * A;

    red[ch] = Wlin[ch] * Bc;
    __syncthreads();
    for (int o = 256; o > 0; o >>= 1) {
        if (ch < o) red[ch] += red[ch + o];
        __syncthreads();
    }
    if (ch == 0) g_zc[0] = blin[0] + red[0];
    __syncthreads();
    red[ch] = Wlin[512 + ch] * Bc;
    __syncthreads();
    for (int o = 256; o > 0; o >>= 1) {
        if (ch < o) red[ch] += red[ch + o];
        __syncthreads();
    }
    if (ch == 0) g_zc[1] = blin[1] + red[0];
}

// ============================================================================
// K4: posterior + gumbel argmax + sampled
// ============================================================================
__global__ void post_k(const float* __restrict__ u,
                       const float* __restrict__ e,
                       float* __restrict__ out) {
    const int s = blockIdx.x * 8 + (threadIdx.x >> 5);
    const int lane = threadIdx.x & 31;
    const int t = s >> 4, b = s & 15;
    const size_t base0 = (size_t)s * HID;
    const size_t base1 = (size_t)(32768 + s) * HID;

    float z0 = 0.f, z1 = 0.f;
#pragma unroll
    for (int i = 0; i < 8; i++) {
        int c = lane + 32 * i;
        float h0 = g_hs[base0 + c];
        float h1 = g_hs[base1 + c];
        z0 += g_wf[c] * h0 + g_wf[256 + c] * h1;
        z1 += g_wf[512 + c] * h0 + g_wf[768 + c] * h1;
    }
#pragma unroll
    for (int o = 16; o > 0; o >>= 1) {
        z0 += __shfl_xor_sync(0xffffffffu, z0, o);
        z1 += __shfl_xor_sync(0xffffffffu, z1, o);
    }
    if (lane == 0) {
        float a0 = (z0 + g_zc[0]) * 0.1f;
        float a1 = (z1 + g_zc[1]) * 0.1f;
        float m = fmaxf(a0, a1);
        float e0 = __expf(a0 - m), e1 = __expf(a1 - m);
        float inv = 1.f / (e0 + e1);
        size_t po = ((size_t)b * T_LEN + t) * 2;
        out[po]     = e0 * inv;
        out[po + 1] = e1 * inv;
        float u0 = u[po], u1 = u[po + 1];
        float gg0 = -logf(-logf(u0 + 1e-20f) + 1e-20f);
        float gg1 = -logf(-logf(u1 + 1e-20f) + 1e-20f);
        int ind = (a1 + gg1 > a0 + gg0) ? 1 : 0;
        g_sampled[b * T_LEN + t] = ind ? e[b * T_LEN + t] : 0.f;
    }
}

// ============================================================================
// K5: three successive median-5 pools
// ============================================================================
__device__ __forceinline__ float median5_(float v0, float v1, float v2,
                                          float v3, float v4) {
#define CSWP(a, b) { float _t = fminf(a, b); b = fmaxf(a, b); a = _t; }
    CSWP(v0, v1); CSWP(v1, v2); CSWP(v2, v3); CSWP(v3, v4);
    CSWP(v0, v1); CSWP(v1, v2); CSWP(v2, v3);
    CSWP(v0, v1); CSWP(v1, v2);
#undef CSWP
    return v2;
}

__global__ void medpool_k(float* __restrict__ out) {
    __shared__ float bufA[2048], bufB[2048];
    const int b = blockIdx.x, tid = threadIdx.x;
    for (int i = tid; i < 2048; i += 256) bufA[i] = g_sampled[b * 2048 + i];
    __syncthreads();
    float* src = bufA;
    float* dst = bufB;
    for (int pass = 0; pass < 3; pass++) {
        for (int i = tid; i < 2048; i += 256) {
            float v[5];
#pragma unroll
            for (int jj = 0; jj < 5; jj++) {
                int j = i + jj - 2;
                j = (j < 0) ? -j : ((j > 2047) ? (4094 - j) : j);
                v[jj] = src[j];
            }
            dst[i] = median5_(v[0], v[1], v[2], v[3], v[4]);
        }
        __syncthreads();
        float* tmp = src; src = dst; dst = tmp;
    }
    for (int i = tid; i < 2048; i += 256)
        out[65536 + b * 2048 + i] = src[i];
}

// ============================================================================
extern "C" void kernel_launch(void* const* d_in, const int* in_sizes, int n_in,
                              void* d_out, int out_size) {
    const float* x      = (const float*)d_in[0];
    const float* e      = (const float*)d_in[1];
    const float* u      = (const float*)d_in[2];
    const float* Wih_f  = (const float*)d_in[3];
    const float* Whh_f  = (const float*)d_in[4];
    const float* bih_f  = (const float*)d_in[5];
    const float* bhh_f  = (const float*)d_in[6];
    const float* Wih_b  = (const float*)d_in[7];
    const float* Whh_b  = (const float*)d_in[8];
    const float* bih_b  = (const float*)d_in[9];
    const float* bhh_b  = (const float*)d_in[10];
    const float* gamma  = (const float*)d_in[11];
    const float* beta   = (const float*)d_in[12];
    const float* Wlin   = (const float*)d_in[13];
    const float* blin   = (const float*)d_in[14];
    float* out = (float*)d_out;

    cudaFuncSetAttribute(gemm_tc, cudaFuncAttributeMaxDynamicSharedMemorySize,
                         GEMM_SMEM);
    cudaFuncSetAttribute(gemm_tc, cudaFuncAttributePreferredSharedMemoryCarveout,
                         100);

    conv_x<<<dim3(64, 16, 16), dim3(32, 8)>>>(x);
    conv_w<<<4096, 256>>>(Wih_f, Wih_b);
    bias_k<<<8, 256>>>(bih_f, bhh_f, bih_b, bhh_b);
    gemm_tc<<<dim3(16, 256), 256, GEMM_SMEM>>>();
    lstm_k<<<128, 1024>>>(Whh_f, Whh_b);
    bn_part<<<32, 512>>>();
    bn_final<<<1, 512>>>(gamma, beta, Wlin, blin);
    post_k<<<4096, 256>>>(u, e, out);
    medpool_k<<<16, 256>>>(out);
}

// round 16
// speedup vs baseline: 1.1623x; 1.1623x over previous
#include <cuda_runtime.h>
#include <cuda_bf16.h>
#include <cstdint>
#include <cstddef>

#define T_LEN 2048
#define BATCH 16
#define HID   256
#define CIN   512
#define GATES 1024              // 4*H per direction
#define NCOL  2048              // gates for both directions
#define MROWS (BATCH * T_LEN)   // 32768

// ---------------- scratch (static device globals; no allocations) ----------
__device__ float g_proj[(size_t)MROWS * NCOL];            // proj + bias folded in
__device__ float g_hs[(size_t)2 * T_LEN * BATCH * HID];   // h outputs [dir][t][b][c]
__device__ float g_part[128 * 512 * 2];                   // BN partial sums
__device__ float g_wf[4 * 512];                           // folded Wlin
__device__ float g_zc[2];                                 // folded bias
__device__ float g_sampled[BATCH * T_LEN];                // sampled pre-median
__device__ float g_bias[NCOL];                            // bih+bhh per gate col
__device__ __align__(16) __nv_bfloat16 g_xt[(size_t)BATCH * T_LEN * CIN]; // x^T bf16
__device__ __align__(16) __nv_bfloat16 g_wc[(size_t)NCOL * CIN];          // W bf16 [n][k]

// ===================== PTX helpers (compute_103-safe only) ==================
__device__ __forceinline__ uint32_t smem_u32(const void* p) {
    return (uint32_t)__cvta_generic_to_shared(p);
}
__device__ __forceinline__ void cp_async16(uint32_t saddr, const void* g) {
    asm volatile("cp.async.cg.shared.global [%0], [%1], 16;"
                 :: "r"(saddr), "l"(g) : "memory");
}
__device__ __forceinline__ void ldsm_x4(uint32_t* r, uint32_t saddr) {
    asm volatile("ldmatrix.sync.aligned.m8n8.x4.shared.b16 {%0,%1,%2,%3}, [%4];"
                 : "=r"(r[0]), "=r"(r[1]), "=r"(r[2]), "=r"(r[3]) : "r"(saddr));
}
__device__ __forceinline__ void mma16816(float* c, const uint32_t* a, const uint32_t* b) {
    asm volatile("mma.sync.aligned.m16n8k16.row.col.f32.bf16.bf16.f32 "
                 "{%0,%1,%2,%3}, {%4,%5,%6,%7}, {%8,%9}, {%0,%1,%2,%3};"
                 : "+f"(c[0]), "+f"(c[1]), "+f"(c[2]), "+f"(c[3])
                 : "r"(a[0]), "r"(a[1]), "r"(a[2]), "r"(a[3]), "r"(b[0]), "r"(b[1]));
}

// ============================================================================
// K0a: transpose+convert x[b][k][t] fp32 -> g_xt[b][t][k] bf16
// ============================================================================
__global__ void conv_x(const float* __restrict__ X) {
    __shared__ float tile[32][33];
    const int b = blockIdx.z;
    const int k0 = blockIdx.y * 32;
    const int t0 = blockIdx.x * 32;
    const int tx = threadIdx.x, ty = threadIdx.y;   // 32 x 8
#pragma unroll
    for (int i = ty; i < 32; i += 8)
        tile[i][tx] = X[((size_t)b * CIN + k0 + i) * T_LEN + t0 + tx];
    __syncthreads();
#pragma unroll
    for (int i = ty; i < 32; i += 8)
        g_xt[((size_t)b * T_LEN + t0 + i) * CIN + k0 + tx] =
            __float2bfloat16(tile[tx][i]);
}

// K0b: convert W rows -> g_wc bf16
__global__ void conv_w(const float* __restrict__ Wf, const float* __restrict__ Wb) {
    size_t i = (size_t)blockIdx.x * 256 + threadIdx.x;   // < 1048576
    const size_t half = (size_t)GATES * CIN;
    if (i < half) g_wc[i] = __float2bfloat16(Wf[i]);
    else          g_wc[i] = __float2bfloat16(Wb[i - half]);
}

// K0c: combined bias per gate column
__global__ void bias_k(const float* __restrict__ bihF, const float* __restrict__ bhhF,
                       const float* __restrict__ bihB, const float* __restrict__ bhhB) {
    int i = blockIdx.x * 256 + threadIdx.x;   // < 2048
    g_bias[i] = (i < GATES) ? (bihF[i] + bhhF[i])
                            : (bihB[i - GATES] + bhhB[i - GATES]);
}

// ============================================================================
// K1: bf16 TN GEMM via ldmatrix + mma.sync, double-buffered cp.async pipeline.
// ============================================================================
#define ASTR 72                       // bf16 elements per smem row
#define A_BYTES (128 * ASTR * 2)      // 18432
#define STAGE_BYTES (2 * A_BYTES)     // 36864
#define GEMM_SMEM (2 * STAGE_BYTES)   // 73728

__global__ void __launch_bounds__(256) gemm_tc() {
    extern __shared__ __align__(16) char gsm[];
    __shared__ float biasS[128];

    const int tid = threadIdx.x;
    const int wid = tid >> 5, lane = tid & 31;
    const int wm = wid >> 1;
    const int wn = wid & 1;
    const int nt = blockIdx.x;            // 0..15
    const int mt = blockIdx.y;            // 0..255
    const int m0 = mt * 128;
    const int bq = m0 >> 11, t0 = m0 & 2047;

    if (tid < 128) biasS[tid] = g_bias[nt * 128 + tid];

    float acc[2][8][4];
#pragma unroll
    for (int i = 0; i < 2; i++)
#pragma unroll
        for (int j = 0; j < 8; j++)
#pragma unroll
            for (int q = 0; q < 4; q++) acc[i][j][q] = 0.f;

    const int a_row = lane & 15, a_koff = (lane >> 4) * 8;
    const int b_nrow = (lane & 7) + ((lane >> 4) << 3);
    const int b_koff = ((lane >> 3) & 1) * 8;

    const uint32_t sb = smem_u32(gsm);

    auto issue = [&](int kc, int stg) {
        uint32_t base = sb + (uint32_t)stg * STAGE_BYTES;
#pragma unroll
        for (int i = 0; i < 4; i++) {
            int idx = tid + i * 256;        // 0..1023
            int row = idx >> 3, seg = idx & 7;
            cp_async16(base + (uint32_t)(row * ASTR + seg * 8) * 2,
                       &g_xt[((size_t)bq * T_LEN + t0 + row) * CIN + kc * 64 + seg * 8]);
            cp_async16(base + A_BYTES + (uint32_t)(row * ASTR + seg * 8) * 2,
                       &g_wc[((size_t)(nt * 128 + row)) * CIN + kc * 64 + seg * 8]);
        }
        asm volatile("cp.async.commit_group;" ::: "memory");
    };

    issue(0, 0);

    for (int kc = 0; kc < 8; kc++) {
        if (kc + 1 < 8) issue(kc + 1, (kc + 1) & 1);
        if (kc + 1 < 8) asm volatile("cp.async.wait_group 1;" ::: "memory");
        else            asm volatile("cp.async.wait_group 0;" ::: "memory");
        __syncthreads();

        uint32_t base = sb + (uint32_t)(kc & 1) * STAGE_BYTES;
#pragma unroll
        for (int ks = 0; ks < 4; ks++) {
            uint32_t afr[2][4];
#pragma unroll
            for (int m2 = 0; m2 < 2; m2++)
                ldsm_x4(afr[m2],
                        base + (uint32_t)((wm * 32 + m2 * 16 + a_row) * ASTR +
                                          ks * 16 + a_koff) * 2);
            uint32_t bfr[8][2];
#pragma unroll
            for (int p = 0; p < 4; p++) {
                uint32_t r[4];
                ldsm_x4(r, base + A_BYTES +
                           (uint32_t)((wn * 64 + p * 16 + b_nrow) * ASTR +
                                      ks * 16 + b_koff) * 2);
                bfr[p * 2][0] = r[0]; bfr[p * 2][1] = r[1];
                bfr[p * 2 + 1][0] = r[2]; bfr[p * 2 + 1][1] = r[3];
            }
#pragma unroll
            for (int m2 = 0; m2 < 2; m2++)
#pragma unroll
                for (int n8 = 0; n8 < 8; n8++)
                    mma16816(acc[m2][n8], afr[m2], bfr[n8]);
        }
        __syncthreads();
    }

#pragma unroll
    for (int m2 = 0; m2 < 2; m2++)
#pragma unroll
        for (int hf = 0; hf < 2; hf++) {
            int row = m0 + wm * 32 + m2 * 16 + hf * 8 + (lane >> 2);
            int cl = wn * 64 + (lane & 3) * 2;
            float* dst = &g_proj[(size_t)row * NCOL + nt * 128 + cl];
#pragma unroll
            for (int n8 = 0; n8 < 8; n8++) {
                float2 v = make_float2(acc[m2][n8][hf * 2] + biasS[cl + n8 * 8],
                                       acc[m2][n8][hf * 2 + 1] + biasS[cl + n8 * 8 + 1]);
                *(float2*)(dst + n8 * 8) = v;
            }
        }
}

// ============================================================================
// K2: LSTM recurrence, v11 — v8 (round-12) + gate consolidation.
// Matvec identical to v8 (HFMA2, 4-chunk ILP, shfl reduce). Partial gate sums
// gathered to smem; gate math + c-state + DSMEM broadcast done by warps 0,1
// only (MUFU/SMSP 1280 -> ~320; ~400 redundant issue slots removed).
// Exact __expf gates; fp32 g_hs (mask is flip-sensitive — round 13 lesson).
// ============================================================================
__device__ __forceinline__ void cluster_sync_() {
    asm volatile("barrier.cluster.arrive.aligned;" ::: "memory");
    asm volatile("barrier.cluster.wait.aligned;" ::: "memory");
}
__device__ __forceinline__ float sigm_(float x) { return 1.f / (1.f + __expf(-x)); }
__device__ __forceinline__ float tanh_(float x) {
    x = fminf(fmaxf(x, -15.f), 15.f);
    float e = __expf(2.f * x);
    return (e - 1.f) / (e + 1.f);
}

#define NCHUNK 4
#define CHLEN  512
#define WARMUP 64
#define SERIAL (CHLEN + WARMUP)      // 576
#define HSEG 40                      // ushorts per 32-cell segment (64B + 16B pad)
#define HBUFW (8 * HSEG)             // 320 ushorts per buffer

__global__ void __cluster_dims__(4, 1, 1) __launch_bounds__(512, 1) lstm_k(
    const float* __restrict__ WhhF, const float* __restrict__ WhhB) {
    __shared__ __align__(16) unsigned short hbuf[NCHUNK * 2 * HBUFW];  // 5120 B
    __shared__ __align__(16) float4 gbuf[NCHUNK][64];                  // 4096 B

    const int tid = threadIdx.x;                 // 512 threads
    const int r = blockIdx.x & 3;                // rank in cluster
    const int chain = blockIdx.x >> 2;           // 0..31
    const int dir = chain >> 4;
    const int b = chain & 15;
    const float* Whh = dir ? WhhB : WhhF;

    const int warp = tid >> 5, lane = tid & 31;
    const int ks = lane & 7;                     // k-slice [ks*32, ks*32+32)
    const int cell = warp * 4 + (lane >> 3);     // 0..63 (matvec role)
    const int gc = r * 64 + cell;

    // weights -> registers: 4 gate rows x 32 k as bf16x2 pairs along k
    __nv_bfloat162 wreg[4][16];
#pragma unroll
    for (int g = 0; g < 4; g++) {
        const int grow = g * 256 + gc;
        const float* wr = Whh + (size_t)grow * HID + ks * 32;
#pragma unroll
        for (int j = 0; j < 16; j++) {
            float2 f2 = *(const float2*)(wr + 2 * j);
            wreg[g][j] = __floats2bfloat162_rn(f2.x, f2.y);
        }
    }

    // gate role (tid < 64): one cell each, owns c-state + proj prefetch
    const int gcell = r * 64 + tid;              // valid for tid < 64
    const int pcolg = dir * GATES + gcell;
    float creg[NCHUNK] = {0.f, 0.f, 0.f, 0.f};
    float pv[NCHUNK][4];
#pragma unroll
    for (int j = 0; j < NCHUNK; j++)
        pv[j][0] = pv[j][1] = pv[j][2] = pv[j][3] = 0.f;
    if (tid < 64) {
#pragma unroll
        for (int j = 0; j < NCHUNK; j++) {
            const int tl = j * CHLEN - WARMUP;   // s = 0
            if (tl >= 0) {
                const int t = dir ? (T_LEN - 1 - tl) : tl;
                const size_t rb = (size_t)(b * T_LEN + t) * NCOL + pcolg;
                pv[j][0] = g_proj[rb];       pv[j][1] = g_proj[rb + 256];
                pv[j][2] = g_proj[rb + 512]; pv[j][3] = g_proj[rb + 768];
            }
        }
    }

    for (int i = tid; i < NCHUNK * 2 * HBUFW / 2; i += 512)
        ((uint32_t*)hbuf)[i] = 0u;
    __syncthreads();
    cluster_sync_();     // peers' hbuf zeroed before DSMEM traffic

    const __nv_bfloat162 bzero = __floats2bfloat162_rn(0.f, 0.f);

    int p = 0;
    for (int s = 0; s < SERIAL; s++) {
        // ---- matvec: 4 chunks back-to-back (max cross-chunk ILP) ----
#pragma unroll
        for (int j = 0; j < NCHUNK; j++) {
            const uint4* hv = (const uint4*)(hbuf + (j * 2 + p) * HBUFW + ks * HSEG);

            float fa0 = 0.f, fa1 = 0.f, fa2 = 0.f, fa3 = 0.f;
#pragma unroll
            for (int half = 0; half < 2; half++) {
                __nv_bfloat162 a0 = bzero, a1 = bzero, a2 = bzero, a3 = bzero;
#pragma unroll
                for (int u = 0; u < 2; u++) {
                    uint4 hq = hv[half * 2 + u];     // 4 bf16x2 = 8 k values
                    __nv_bfloat162 h0 = *(__nv_bfloat162*)&hq.x;
                    __nv_bfloat162 h1 = *(__nv_bfloat162*)&hq.y;
                    __nv_bfloat162 h2 = *(__nv_bfloat162*)&hq.z;
                    __nv_bfloat162 h3 = *(__nv_bfloat162*)&hq.w;
                    const int base = half * 8 + u * 4;
                    a0 = __hfma2(wreg[0][base], h0, a0);
                    a0 = __hfma2(wreg[0][base + 1], h1, a0);
                    a0 = __hfma2(wreg[0][base + 2], h2, a0);
                    a0 = __hfma2(wreg[0][base + 3], h3, a0);
                    a1 = __hfma2(wreg[1][base], h0, a1);
                    a1 = __hfma2(wreg[1][base + 1], h1, a1);
                    a1 = __hfma2(wreg[1][base + 2], h2, a1);
                    a1 = __hfma2(wreg[1][base + 3], h3, a1);
                    a2 = __hfma2(wreg[2][base], h0, a2);
                    a2 = __hfma2(wreg[2][base + 1], h1, a2);
                    a2 = __hfma2(wreg[2][base + 2], h2, a2);
                    a2 = __hfma2(wreg[2][base + 3], h3, a2);
                    a3 = __hfma2(wreg[3][base], h0, a3);
                    a3 = __hfma2(wreg[3][base + 1], h1, a3);
                    a3 = __hfma2(wreg[3][base + 2], h2, a3);
                    a3 = __hfma2(wreg[3][base + 3], h3, a3);
                }
                float2 f;
                f = __bfloat1622float2(a0); fa0 += f.x + f.y;
                f = __bfloat1622float2(a1); fa1 += f.x + f.y;
                f = __bfloat1622float2(a2); fa2 += f.x + f.y;
                f = __bfloat1622float2(a3); fa3 += f.x + f.y;
            }
#pragma unroll
            for (int m = 1; m < 8; m <<= 1) {
                fa0 += __shfl_xor_sync(0xffffffffu, fa0, m);
                fa1 += __shfl_xor_sync(0xffffffffu, fa1, m);
                fa2 += __shfl_xor_sync(0xffffffffu, fa2, m);
                fa3 += __shfl_xor_sync(0xffffffffu, fa3, m);
            }
            if (ks == 0)
                gbuf[j][cell] = make_float4(fa0, fa1, fa2, fa3);
        }
        __syncthreads();   // gbuf visible to gate warps

        // ---- gate phase: warps 0,1 only; one cell per thread, 4 chunks ----
        if (tid < 64) {
#pragma unroll
            for (int j = 0; j < NCHUNK; j++) {
                float4 A = gbuf[j][tid];
                const int tl = j * CHLEN - WARMUP + s;
                const float gi = A.x + pv[j][0];
                const float gf = A.y + pv[j][1];
                const float gg = A.z + pv[j][2];
                const float go = A.w + pv[j][3];
                if (s + 1 < SERIAL) {      // prefetch next step's proj row
                    const int tn_log = tl + 1;
                    if (tn_log >= 0) {
                        const int tn = dir ? (T_LEN - 1 - tn_log) : tn_log;
                        const size_t rb = (size_t)(b * T_LEN + tn) * NCOL + pcolg;
                        pv[j][0] = g_proj[rb];       pv[j][1] = g_proj[rb + 256];
                        pv[j][2] = g_proj[rb + 512]; pv[j][3] = g_proj[rb + 768];
                    }
                }
                float hval = 0.f;
                if (tl >= 0) {
                    const float iv = sigm_(gi);
                    const float fv = sigm_(gf);
                    const float gv = tanh_(gg);
                    const float ov = sigm_(go);
                    creg[j] = fv * creg[j] + iv * gv;
                    hval = ov * tanh_(creg[j]);
                    if (s >= WARMUP) {
                        const int te = dir ? (T_LEN - 1 - tl) : tl;
                        g_hs[(size_t)((dir * T_LEN + te) * BATCH + b) * HID + gcell] =
                            hval;
                    }
                }
                // pack adjacent cells (even tid with tid+1) and store b32
                uint32_t us =
                    (uint32_t)__bfloat16_as_ushort(__float2bfloat16(hval));
                uint32_t other = __shfl_down_sync(0xffffffffu, us, 1);
                if ((tid & 1) == 0) {
                    const uint32_t pair = us | (other << 16);
                    const int boff = (j * 2 + (p ^ 1)) * HBUFW +
                                     (gcell >> 5) * HSEG + (gcell & 31);
                    *(uint32_t*)&hbuf[boff] = pair;      // local
                    const uint32_t la = smem_u32(&hbuf[boff]);
#pragma unroll
                    for (int pc = 0; pc < 4; pc++) {
                        if (pc == r) continue;
                        uint32_t ra;
                        asm("mapa.shared::cluster.u32 %0, %1, %2;"
                            : "=r"(ra) : "r"(la), "r"(pc));
                        asm volatile("st.shared::cluster.u32 [%0], %1;"
                                     :: "r"(ra), "r"(pair) : "memory");
                    }
                }
            }
        }
        cluster_sync_();   // release gate warps' DSMEM h / acquire peers'
        p ^= 1;
    }
}

// ============================================================================
// K3a/K3b: BN stats + fold into Linear
// ============================================================================
__global__ void bn_part() {
    const int ch = threadIdx.x;
    const int dir = ch >> 8, cc = ch & 255;
    const int s0 = blockIdx.x * 1024;
    float sum = 0.f, sq = 0.f;
    const size_t base = (size_t)dir * T_LEN * BATCH * HID + cc;
#pragma unroll 4
    for (int i = 0; i < 1024; i++) {
        float v = g_hs[base + (size_t)(s0 + i) * HID];
        sum += v; sq += v * v;
    }
    g_part[((size_t)blockIdx.x * 512 + ch) * 2]     = sum;
    g_part[((size_t)blockIdx.x * 512 + ch) * 2 + 1] = sq;
}

__global__ void bn_final(const float* __restrict__ gamma,
                         const float* __restrict__ beta,
                         const float* __restrict__ Wlin,
                         const float* __restrict__ blin) {
    __shared__ float red[512];
    const int ch = threadIdx.x;
    double s = 0.0, q = 0.0;
#pragma unroll 8
    for (int i = 0; i < 32; i++) {
        s += (double)g_part[((size_t)i * 512 + ch) * 2];
        q += (double)g_part[((size_t)i * 512 + ch) * 2 + 1];
    }
    const double n = 32768.0;
    float mean = (float)(s / n);
    float var  = (float)(q / n - (s / n) * (s / n));
    float A  = gamma[ch] * rsqrtf(var + 1e-5f);
    float Bc = beta[ch] - mean * A;

    g_wf[ch]       = Wlin[ch] * A;
    g_wf[512 + ch] = Wlin[512 + ch] * A;

    red[ch] = Wlin[ch] * Bc;
    __syncthreads();
    for (int o = 256; o > 0; o >>= 1) {
        if (ch < o) red[ch] += red[ch + o];
        __syncthreads();
    }
    if (ch == 0) g_zc[0] = blin[0] + red[0];
    __syncthreads();
    red[ch] = Wlin[512 + ch] * Bc;
    __syncthreads();
    for (int o = 256; o > 0; o >>= 1) {
        if (ch < o) red[ch] += red[ch + o];
        __syncthreads();
    }
    if (ch == 0) g_zc[1] = blin[1] + red[0];
}

// ============================================================================
// K4: posterior + gumbel argmax + sampled
// ============================================================================
__global__ void post_k(const float* __restrict__ u,
                       const float* __restrict__ e,
                       float* __restrict__ out) {
    const int s = blockIdx.x * 8 + (threadIdx.x >> 5);
    const int lane = threadIdx.x & 31;
    const int t = s >> 4, b = s & 15;
    const size_t base0 = (size_t)s * HID;
    const size_t base1 = (size_t)(32768 + s) * HID;

    float z0 = 0.f, z1 = 0.f;
#pragma unroll
    for (int i = 0; i < 8; i++) {
        int c = lane + 32 * i;
        float h0 = g_hs[base0 + c];
        float h1 = g_hs[base1 + c];
        z0 += g_wf[c] * h0 + g_wf[256 + c] * h1;
        z1 += g_wf[512 + c] * h0 + g_wf[768 + c] * h1;
    }
#pragma unroll
    for (int o = 16; o > 0; o >>= 1) {
        z0 += __shfl_xor_sync(0xffffffffu, z0, o);
        z1 += __shfl_xor_sync(0xffffffffu, z1, o);
    }
    if (lane == 0) {
        float a0 = (z0 + g_zc[0]) * 0.1f;
        float a1 = (z1 + g_zc[1]) * 0.1f;
        float m = fmaxf(a0, a1);
        float e0 = __expf(a0 - m), e1 = __expf(a1 - m);
        float inv = 1.f / (e0 + e1);
        size_t po = ((size_t)b * T_LEN + t) * 2;
        out[po]     = e0 * inv;
        out[po + 1] = e1 * inv;
        float u0 = u[po], u1 = u[po + 1];
        float gg0 = -logf(-logf(u0 + 1e-20f) + 1e-20f);
        float gg1 = -logf(-logf(u1 + 1e-20f) + 1e-20f);
        int ind = (a1 + gg1 > a0 + gg0) ? 1 : 0;
        g_sampled[b * T_LEN + t] = ind ? e[b * T_LEN + t] : 0.f;
    }
}

// ============================================================================
// K5: three successive median-5 pools
// ============================================================================
__device__ __forceinline__ float median5_(float v0, float v1, float v2,
                                          float v3, float v4) {
#define CSWP(a, b) { float _t = fminf(a, b); b = fmaxf(a, b); a = _t; }
    CSWP(v0, v1); CSWP(v1, v2); CSWP(v2, v3); CSWP(v3, v4);
    CSWP(v0, v1); CSWP(v1, v2); CSWP(v2, v3);
    CSWP(v0, v1); CSWP(v1, v2);
#undef CSWP
    return v2;
}

__global__ void medpool_k(float* __restrict__ out) {
    __shared__ float bufA[2048], bufB[2048];
    const int b = blockIdx.x, tid = threadIdx.x;
    for (int i = tid; i < 2048; i += 256) bufA[i] = g_sampled[b * 2048 + i];
    __syncthreads();
    float* src = bufA;
    float* dst = bufB;
    for (int pass = 0; pass < 3; pass++) {
        for (int i = tid; i < 2048; i += 256) {
            float v[5];
#pragma unroll
            for (int jj = 0; jj < 5; jj++) {
                int j = i + jj - 2;
                j = (j < 0) ? -j : ((j > 2047) ? (4094 - j) : j);
                v[jj] = src[j];
            }
            dst[i] = median5_(v[0], v[1], v[2], v[3], v[4]);
        }
        __syncthreads();
        float* tmp = src; src = dst; dst = tmp;
    }
    for (int i = tid; i < 2048; i += 256)
        out[65536 + b * 2048 + i] = src[i];
}

// ============================================================================
extern "C" void kernel_launch(void* const* d_in, const int* in_sizes, int n_in,
                              void* d_out, int out_size) {
    const float* x      = (const float*)d_in[0];
    const float* e      = (const float*)d_in[1];
    const float* u      = (const float*)d_in[2];
    const float* Wih_f  = (const float*)d_in[3];
    const float* Whh_f  = (const float*)d_in[4];
    const float* bih_f  = (const float*)d_in[5];
    const float* bhh_f  = (const float*)d_in[6];
    const float* Wih_b  = (const float*)d_in[7];
    const float* Whh_b  = (const float*)d_in[8];
    const float* bih_b  = (const float*)d_in[9];
    const float* bhh_b  = (const float*)d_in[10];
    const float* gamma  = (const float*)d_in[11];
    const float* beta   = (const float*)d_in[12];
    const float* Wlin   = (const float*)d_in[13];
    const float* blin   = (const float*)d_in[14];
    float* out = (float*)d_out;

    cudaFuncSetAttribute(gemm_tc, cudaFuncAttributeMaxDynamicSharedMemorySize,
                         GEMM_SMEM);

    conv_x<<<dim3(64, 16, 16), dim3(32, 8)>>>(x);
    conv_w<<<4096, 256>>>(Wih_f, Wih_b);
    bias_k<<<8, 256>>>(bih_f, bhh_f, bih_b, bhh_b);
    gemm_tc<<<dim3(16, 256), 256, GEMM_SMEM>>>();
    lstm_k<<<128, 512>>>(Whh_f, Whh_b);
    bn_part<<<32, 512>>>();
    bn_final<<<1, 512>>>(gamma, beta, Wlin, blin);
    post_k<<<4096, 256>>>(u, e, out);
    medpool_k<<<16, 256>>>(out);
}